// round 8
// baseline (speedup 1.0000x reference)
#include <cuda_runtime.h>
#include <math.h>

#define NJ     23
#define NP     16
#define NPAIR  8
#define VTOT   500000
#define V3     1500000
#define OUT_JOFF (NP * V3)
#define VPB    128            // vertices per block

struct Ptrs { const float* p[11]; };

__constant__ int   c_PAR[NJ]  = {-1,0,1,1,3,4,5,4,7,4,9,1,11,12,13,12,15,12,17,0,19,0,21};
__constant__ int   c_SLOT[NJ] = { 0,-1,-1, 1, 2, 3,-1, 4,-1, 5,-1, 6, 7, 8,-1, 9,-1,10,-1,-1,-1,-1,-1};
#define QU 0.7853981633974483f
#define HA 1.5707963267948966f
__constant__ float c_SC[NJ]   = {QU,0,0,HA,HA,QU,0,QU,0,QU,0,HA,HA,QU,0,QU,0,QU,0,0,0,0,0};
// kinematic tree by depth level (parents of level-l joints are in levels < l)
__constant__ int c_LVLJ[6][6] = {{0,0,0,0,0,0},{1,19,21,0,0,0},{2,3,11,20,22,0},
                                 {4,12,0,0,0,0},{5,7,9,13,15,17},{6,8,10,14,16,18}};
__constant__ int c_LVLC[6]    = {1,3,5,2,6,6};

// Pose-pair-interleaved skinning matrices: g_A2[(j*8+pair)*12 + a*4+b]
__device__ float2 g_A2[NJ * NPAIR * 12];
__device__ float2 g_shift2[NPAIR * 3];
__device__ int    g_flag;          // 0 at load; set once by block 0

union F2U { float2 f; unsigned long long u; };
__device__ __forceinline__ float2 ffma2(float2 a, float2 b, float2 c)
{
    F2U A, B, C, D;
    A.f = a; B.f = b; C.f = c;
    asm("fma.rn.f32x2 %0, %1, %2, %3;"
        : "=l"(D.u) : "l"(A.u), "l"(B.u), "l"(C.u));
    return D.f;
}

// shared carving (floats):
//   main: sA2 = [0, 4416)   (2208 float2, 17664B)
//         sW  = [4416, 7360) (128*23 floats, 11776B)
//         sSh = [7360, 7408) (24 float2)
//   prep: Rsh = [0, 3312)    (23*16*9)
//         Gsh = [3312, 7728) (16*23*12)
#define SBUF_FLOATS 7776

__global__ void __launch_bounds__(256, 3)
lbs_all(const float* __restrict__ verts,
        const float* __restrict__ W,
        const float* __restrict__ joints,
        const float* __restrict__ disp,
        const float* __restrict__ rnd,
        Ptrs pp,
        float* __restrict__ out)
{
    __shared__ __align__(16) float sBuf[SBUF_FLOATS];
    __shared__ float sShP[NP * 3];

    const int tid  = threadIdx.x;
    const int base = blockIdx.x * VPB;

    if (blockIdx.x == 0) {
        // =================== PREP (block 0 only) ===================
        float* Rsh = sBuf;          // R[(j*16+p)*9 + e]
        float* Gsh = sBuf + 3312;   // G[(p*23+j)*12 + a*4+b]

        // Phase A: Rodrigues for all (j,p) + shifts
        for (int t = tid; t < NJ * NP; t += 256) {
            const int j = t >> 4, p = t & 15;
            float rx = 0.f, ry = 0.f, rz = 0.f;
            const int s = c_SLOT[j];
            if (s >= 0) {
                const float* prm = pp.p[s] + p * 3;
                const float sc = c_SC[j];
                rx = sc * tanhf(prm[0]);
                ry = sc * tanhf(prm[1]);
                rz = sc * tanhf(prm[2]);
            }
            const float ang = sqrtf(rx*rx + ry*ry + rz*rz + 1e-16f);
            const float ax = rx / ang, ay = ry / ang, az = rz / ang;
            const float sn = sinf(ang), cs = cosf(ang), tt = 1.0f - cs;
            float* R = Rsh + (j*NP + p) * 9;
            R[0] = 1.f - tt*(ay*ay + az*az); R[1] = -sn*az + tt*ax*ay; R[2] =  sn*ay + tt*ax*az;
            R[3] =  sn*az + tt*ax*ay; R[4] = 1.f - tt*(ax*ax + az*az); R[5] = -sn*ax + tt*ay*az;
            R[6] = -sn*ay + tt*ax*az; R[7] =  sn*ax + tt*ay*az; R[8] = 1.f - tt*(ax*ax + ay*ay);
        }
        if (tid < NP) {
            const int p = tid;
            const float s0 = rnd[p*3+0] + 3.0f * tanhf(disp[p*3+0]);
            const float s1 = rnd[p*3+1] + 3.0f * tanhf(disp[p*3+1]);
            const float s2 = rnd[p*3+2] + 3.0f * tanhf(disp[p*3+2]);
            sShP[p*3+0] = s0; sShP[p*3+1] = s1; sShP[p*3+2] = s2;
            const int pair = p >> 1, lane = p & 1;
            ((float*)&g_shift2[pair*3+0])[lane] = s0;
            ((float*)&g_shift2[pair*3+1])[lane] = s1;
            ((float*)&g_shift2[pair*3+2])[lane] = s2;
        }
        __syncthreads();

        // Phase B: chain composition by tree level
        for (int l = 0; l < 6; l++) {
            const int p = tid / 6, s = tid - p * 6;
            if (p < NP && s < c_LVLC[l]) {
                const int j = c_LVLJ[l][s];
                const float* R = Rsh + (j*NP + p) * 9;
                float* Gj = Gsh + (p*NJ + j) * 12;
                if (j == 0) {
                    Gj[0] = R[0]; Gj[1] = R[1]; Gj[2]  = R[2]; Gj[3]  = joints[0];
                    Gj[4] = R[3]; Gj[5] = R[4]; Gj[6]  = R[5]; Gj[7]  = joints[1];
                    Gj[8] = R[6]; Gj[9] = R[7]; Gj[10] = R[8]; Gj[11] = joints[2];
                } else {
                    const int q = c_PAR[j];
                    const float rel0 = joints[3*j+0] - joints[3*q+0];
                    const float rel1 = joints[3*j+1] - joints[3*q+1];
                    const float rel2 = joints[3*j+2] - joints[3*q+2];
                    const float* Gq = Gsh + (p*NJ + q) * 12;
                    #pragma unroll
                    for (int a = 0; a < 3; a++) {
                        const float g0 = Gq[a*4+0], g1 = Gq[a*4+1], g2 = Gq[a*4+2], g3 = Gq[a*4+3];
                        Gj[a*4+0] = g0*R[0] + g1*R[3] + g2*R[6];
                        Gj[a*4+1] = g0*R[1] + g1*R[4] + g2*R[7];
                        Gj[a*4+2] = g0*R[2] + g1*R[5] + g2*R[8];
                        Gj[a*4+3] = g0*rel0 + g1*rel1 + g2*rel2 + g3;
                    }
                }
            }
            __syncthreads();
        }

        // Phase C: posed joints + A to global
        for (int t = tid; t < NJ * NP; t += 256) {
            const int j = t >> 4, p = t & 15;
            const float* Gj = Gsh + (p*NJ + j) * 12;
            out[OUT_JOFF + (p*NJ + j)*3 + 0] = Gj[3]  + sShP[p*3+0];
            out[OUT_JOFF + (p*NJ + j)*3 + 1] = Gj[7]  + sShP[p*3+1];
            out[OUT_JOFF + (p*NJ + j)*3 + 2] = Gj[11] + sShP[p*3+2];
            const float jx = joints[3*j], jy = joints[3*j+1], jz = joints[3*j+2];
            const int pair = p >> 1, lane = p & 1;
            float* dst = (float*)&g_A2[(j*NPAIR + pair)*12];
            #pragma unroll
            for (int a = 0; a < 3; a++) {
                const float g0 = Gj[a*4+0], g1 = Gj[a*4+1], g2 = Gj[a*4+2];
                const float At = Gj[a*4+3] - (g0*jx + g1*jy + g2*jz);
                dst[(a*4+0)*2 + lane] = g0;
                dst[(a*4+1)*2 + lane] = g1;
                dst[(a*4+2)*2 + lane] = g2;
                dst[(a*4+3)*2 + lane] = At;
            }
        }
        __threadfence();
        __syncthreads();
        if (tid == 0) atomicExch(&g_flag, 1);
    }

    // =================== STAGE (all blocks) ===================
    float2* sA2 = (float2*)sBuf;            // 2208 float2
    float*  sW  = sBuf + 4416;              // 128*23 floats
    float2* sSh = (float2*)(sBuf + 7360);   // 24 float2

    // weight tile first (overlaps flag wait with DRAM latency)
    {
        const int nv  = min(VPB, VTOT - base);
        const int nf4 = (nv * NJ) >> 2;      // nv*23 divisible by 4 for nv=128/32
        float4* d = (float4*)sW;
        const float4* s = (const float4*)(W + (size_t)base * NJ);
        for (int i = tid; i < nf4; i += 256) d[i] = s[i];
    }
    if (tid == 0) {
        while (atomicAdd(&g_flag, 0) == 0) __nanosleep(256);
    }
    __syncthreads();
    __threadfence();
    {
        float4* d = (float4*)sA2;
        const float4* s = (const float4*)g_A2;
        for (int i = tid; i < (NJ * NPAIR * 12) / 2; i += 256) d[i] = s[i];
    }
    if (tid < NPAIR * 3) sSh[tid] = g_shift2[tid];
    __syncthreads();

    // =================== MAIN ===================
    // thread = 1 pose-pair x 4 vertices; warp-uniform pg -> broadcast A loads
    const int vid = tid & 31;
    const int pg  = tid >> 5;              // 0..7 pose pair
    const int v0  = base + vid;            // vertices v0 + {0,32,64,96}

    float2 x[4], y[4], z[4];
    #pragma unroll
    for (int u = 0; u < 4; u++) {
        int v = v0 + 32*u; if (v >= VTOT) v = VTOT - 1;   // clamp; stores guarded
        const float a = __ldg(&verts[v*3+0]);
        const float b = __ldg(&verts[v*3+1]);
        const float c = __ldg(&verts[v*3+2]);
        x[u] = make_float2(a, a); y[u] = make_float2(b, b); z[u] = make_float2(c, c);
    }

    float2 acc[3][4];
    #pragma unroll
    for (int r = 0; r < 3; r++)
        #pragma unroll
        for (int u = 0; u < 4; u++)
            acc[r][u] = make_float2(0.f, 0.f);

    const float* sWp = sW + vid * NJ;

    #pragma unroll 1
    for (int j = 0; j < NJ; j++) {
        float2 w[4];
        #pragma unroll
        for (int u = 0; u < 4; u++) {
            const float ww = sWp[u * (32*NJ) + j];
            w[u] = make_float2(ww, ww);
        }
        const float4* Aj = (const float4*)(sA2 + (j*NPAIR + pg)*12);
        const float4 q0 = Aj[0], q1 = Aj[1], q2 = Aj[2];
        const float4 q3 = Aj[3], q4 = Aj[4], q5 = Aj[5];
        const float2 m00 = make_float2(q0.x,q0.y), m01 = make_float2(q0.z,q0.w);
        const float2 m02 = make_float2(q1.x,q1.y), m03 = make_float2(q1.z,q1.w);
        const float2 m10 = make_float2(q2.x,q2.y), m11 = make_float2(q2.z,q2.w);
        const float2 m12 = make_float2(q3.x,q3.y), m13 = make_float2(q3.z,q3.w);
        const float2 m20 = make_float2(q4.x,q4.y), m21 = make_float2(q4.z,q4.w);
        const float2 m22 = make_float2(q5.x,q5.y), m23 = make_float2(q5.z,q5.w);

        #pragma unroll
        for (int u = 0; u < 4; u++) {
            float2 t;
            t = ffma2(m00, x[u], ffma2(m01, y[u], ffma2(m02, z[u], m03)));
            acc[0][u] = ffma2(w[u], t, acc[0][u]);
            t = ffma2(m10, x[u], ffma2(m11, y[u], ffma2(m12, z[u], m13)));
            acc[1][u] = ffma2(w[u], t, acc[1][u]);
            t = ffma2(m20, x[u], ffma2(m21, y[u], ffma2(m22, z[u], m23)));
            acc[2][u] = ffma2(w[u], t, acc[2][u]);
        }
    }

    // Epilogue
    const int p0 = 2 * pg;
    #pragma unroll
    for (int a = 0; a < 3; a++) {
        const float2 s = sSh[pg*3 + a];
        #pragma unroll
        for (int u = 0; u < 4; u++) {
            const int v = v0 + 32*u;
            if (v < VTOT) {
                out[ p0   *V3 + v*3 + a] = acc[a][u].x + s.x;
                out[(p0+1)*V3 + v*3 + a] = acc[a][u].y + s.y;
            }
        }
    }
}

// ---------------------------------------------------------------------------
extern "C" void kernel_launch(void* const* d_in, const int* in_sizes, int n_in,
                              void* d_out, int out_size)
{
    const float* vertices = (const float*)d_in[0];
    const float* joints   = (const float*)d_in[1];
    const float* weights  = (const float*)d_in[2];
    const float* disp     = (const float*)d_in[3];
    const float* rnd      = (const float*)d_in[4];
    Ptrs pp;
    for (int i = 0; i < 11; i++) pp.p[i] = (const float*)d_in[5 + i];
    float* out = (float*)d_out;

    const int nblocks = (VTOT + VPB - 1) / VPB;   // 3907
    lbs_all<<<nblocks, 256>>>(vertices, weights, joints, disp, rnd, pp, out);
}

// round 9
// speedup vs baseline: 1.5508x; 1.5508x over previous
#include <cuda_runtime.h>
#include <math.h>

#define NJ     23
#define NP     16
#define NPAIR  8
#define VTOT   500000
#define V3     1500000
#define OUT_JOFF (NP * V3)
#define VPB    256            // vertices per block

struct Ptrs { const float* p[11]; };

__constant__ int   c_PAR[NJ]  = {-1,0,1,1,3,4,5,4,7,4,9,1,11,12,13,12,15,12,17,0,19,0,21};
__constant__ int   c_SLOT[NJ] = { 0,-1,-1, 1, 2, 3,-1, 4,-1, 5,-1, 6, 7, 8,-1, 9,-1,10,-1,-1,-1,-1,-1};
#define QU 0.7853981633974483f
#define HA 1.5707963267948966f
__constant__ float c_SC[NJ]   = {QU,0,0,HA,HA,QU,0,QU,0,QU,0,HA,HA,QU,0,QU,0,QU,0,0,0,0,0};
// kinematic tree by depth level (parents of level-l joints are in levels < l)
__constant__ int c_LVLJ[6][6] = {{0,0,0,0,0,0},{1,19,21,0,0,0},{2,3,11,20,22,0},
                                 {4,12,0,0,0,0},{5,7,9,13,15,17},{6,8,10,14,16,18}};
__constant__ int c_LVLC[6]    = {1,3,5,2,6,6};

// Pose-pair-interleaved skinning matrices: g_A2[(j*8+pair)*12 + a*4+b]
__device__ float2 g_A2[NJ * NPAIR * 12];
__device__ float2 g_shift2[NPAIR * 3];
__device__ int    g_flag;          // 0 at load; set once by block 0

union F2U { float2 f; unsigned long long u; };
__device__ __forceinline__ float2 ffma2(float2 a, float2 b, float2 c)
{
    F2U A, B, C, D;
    A.f = a; B.f = b; C.f = c;
    asm("fma.rn.f32x2 %0, %1, %2, %3;"
        : "=l"(D.u) : "l"(A.u), "l"(B.u), "l"(C.u));
    return D.f;
}

// Shared buffer carving (floats):
//   main: sA2 = [0, 4416)     2208 float2 (17664 B)
//         sW  = [4416, 10304) 256*23 floats (23552 B)
//   prep: Rsh = [0, 3312)     23*16*9
//         Gsh = [3312, 7728)  16*23*12   (both inside the 10304-float buffer)
#define SBUF_FLOATS 10304

__global__ void __launch_bounds__(256, 3)
lbs_all(const float* __restrict__ verts,
        const float* __restrict__ W,
        const float* __restrict__ joints,
        const float* __restrict__ disp,
        const float* __restrict__ rnd,
        Ptrs pp,
        float* __restrict__ out)
{
    __shared__ __align__(16) float sBuf[SBUF_FLOATS];
    __shared__ float2 sSh[NPAIR * 3];
    __shared__ float  sShP[NP * 3];

    const int tid  = threadIdx.x;
    const int base = blockIdx.x * VPB;

    if (blockIdx.x == 0) {
        // =================== PREP (block 0 only, parallel, ~1-2us) ===========
        float* Rsh = sBuf;          // R[(j*16+p)*9 + e]
        float* Gsh = sBuf + 3312;   // G[(p*23+j)*12 + a*4+b]

        // Phase A: Rodrigues for all (j,p) + shifts
        for (int t = tid; t < NJ * NP; t += 256) {
            const int j = t >> 4, p = t & 15;
            float rx = 0.f, ry = 0.f, rz = 0.f;
            const int s = c_SLOT[j];
            if (s >= 0) {
                const float* prm = pp.p[s] + p * 3;
                const float sc = c_SC[j];
                rx = sc * tanhf(prm[0]);
                ry = sc * tanhf(prm[1]);
                rz = sc * tanhf(prm[2]);
            }
            const float ang = sqrtf(rx*rx + ry*ry + rz*rz + 1e-16f);
            const float ax = rx / ang, ay = ry / ang, az = rz / ang;
            const float sn = sinf(ang), cs = cosf(ang), tt = 1.0f - cs;
            float* R = Rsh + (j*NP + p) * 9;
            R[0] = 1.f - tt*(ay*ay + az*az); R[1] = -sn*az + tt*ax*ay; R[2] =  sn*ay + tt*ax*az;
            R[3] =  sn*az + tt*ax*ay; R[4] = 1.f - tt*(ax*ax + az*az); R[5] = -sn*ax + tt*ay*az;
            R[6] = -sn*ay + tt*ax*az; R[7] =  sn*ax + tt*ay*az; R[8] = 1.f - tt*(ax*ax + ay*ay);
        }
        if (tid < NP) {
            const int p = tid;
            const float s0 = rnd[p*3+0] + 3.0f * tanhf(disp[p*3+0]);
            const float s1 = rnd[p*3+1] + 3.0f * tanhf(disp[p*3+1]);
            const float s2 = rnd[p*3+2] + 3.0f * tanhf(disp[p*3+2]);
            sShP[p*3+0] = s0; sShP[p*3+1] = s1; sShP[p*3+2] = s2;
            const int pair = p >> 1, lane = p & 1;
            ((float*)&g_shift2[pair*3+0])[lane] = s0;
            ((float*)&g_shift2[pair*3+1])[lane] = s1;
            ((float*)&g_shift2[pair*3+2])[lane] = s2;
        }
        __syncthreads();

        // Phase B: chain composition by tree level (6 barrier-separated steps)
        for (int l = 0; l < 6; l++) {
            const int p = tid / 6, s = tid - p * 6;
            if (p < NP && s < c_LVLC[l]) {
                const int j = c_LVLJ[l][s];
                const float* R = Rsh + (j*NP + p) * 9;
                float* Gj = Gsh + (p*NJ + j) * 12;
                if (j == 0) {
                    Gj[0] = R[0]; Gj[1] = R[1]; Gj[2]  = R[2]; Gj[3]  = joints[0];
                    Gj[4] = R[3]; Gj[5] = R[4]; Gj[6]  = R[5]; Gj[7]  = joints[1];
                    Gj[8] = R[6]; Gj[9] = R[7]; Gj[10] = R[8]; Gj[11] = joints[2];
                } else {
                    const int q = c_PAR[j];
                    const float rel0 = joints[3*j+0] - joints[3*q+0];
                    const float rel1 = joints[3*j+1] - joints[3*q+1];
                    const float rel2 = joints[3*j+2] - joints[3*q+2];
                    const float* Gq = Gsh + (p*NJ + q) * 12;
                    #pragma unroll
                    for (int a = 0; a < 3; a++) {
                        const float g0 = Gq[a*4+0], g1 = Gq[a*4+1], g2 = Gq[a*4+2], g3 = Gq[a*4+3];
                        Gj[a*4+0] = g0*R[0] + g1*R[3] + g2*R[6];
                        Gj[a*4+1] = g0*R[1] + g1*R[4] + g2*R[7];
                        Gj[a*4+2] = g0*R[2] + g1*R[5] + g2*R[8];
                        Gj[a*4+3] = g0*rel0 + g1*rel1 + g2*rel2 + g3;
                    }
                }
            }
            __syncthreads();
        }

        // Phase C: posed joints out + A matrices to global
        for (int t = tid; t < NJ * NP; t += 256) {
            const int j = t >> 4, p = t & 15;
            const float* Gj = Gsh + (p*NJ + j) * 12;
            out[OUT_JOFF + (p*NJ + j)*3 + 0] = Gj[3]  + sShP[p*3+0];
            out[OUT_JOFF + (p*NJ + j)*3 + 1] = Gj[7]  + sShP[p*3+1];
            out[OUT_JOFF + (p*NJ + j)*3 + 2] = Gj[11] + sShP[p*3+2];
            const float jx = joints[3*j], jy = joints[3*j+1], jz = joints[3*j+2];
            const int pair = p >> 1, lane = p & 1;
            float* dst = (float*)&g_A2[(j*NPAIR + pair)*12];
            #pragma unroll
            for (int a = 0; a < 3; a++) {
                const float g0 = Gj[a*4+0], g1 = Gj[a*4+1], g2 = Gj[a*4+2];
                const float At = Gj[a*4+3] - (g0*jx + g1*jy + g2*jz);
                dst[(a*4+0)*2 + lane] = g0;
                dst[(a*4+1)*2 + lane] = g1;
                dst[(a*4+2)*2 + lane] = g2;
                dst[(a*4+3)*2 + lane] = At;
            }
        }
        __threadfence();        // publish g_A2 / g_shift2 / joint outputs
        __syncthreads();
        if (tid == 0) atomicExch(&g_flag, 1);
        // falls through to stage+main like every other block (flag already set)
    }

    // =================== STAGE (all blocks) ===================
    float2* sA2 = (float2*)sBuf;        // 2208 float2
    float*  sW  = sBuf + 4416;          // 256*23 floats

    // weight tile first (overlaps the flag wait with DRAM latency)
    {
        const int nv  = min(VPB, VTOT - base);
        const int nf4 = (nv * NJ) >> 2;      // nv*23 divisible by 4 (nv=256 or 160)
        float4* d = (float4*)sW;
        const float4* s = (const float4*)(W + (size_t)base * NJ);
        for (int i = tid; i < nf4; i += 256) d[i] = s[i];
    }
    if (tid == 0) {
        while (atomicAdd(&g_flag, 0) == 0) __nanosleep(256);
    }
    __syncthreads();
    __threadfence();   // order subsequent g_A2 loads after the flag read
    {
        float4* d = (float4*)sA2;
        const float4* s = (const float4*)g_A2;
        for (int i = tid; i < (NJ * NPAIR * 12) / 2; i += 256) d[i] = s[i];
    }
    if (tid < NPAIR * 3) sSh[tid] = g_shift2[tid];
    __syncthreads();

    // =================== MAIN (identical to R6's 109.4us loop) ===============
    const int vid = tid & 63;
    const int pg  = tid >> 6;          // 0..3 -> pose pairs {2pg, 2pg+1}
    const int v0  = base + vid;        // this thread: vertices v0 + {0,64,128,192}

    float2 x[4], y[4], z[4];
    #pragma unroll
    for (int u = 0; u < 4; u++) {
        int v = v0 + 64*u; if (v >= VTOT) v = VTOT - 1;   // clamp; stores guarded
        const float a = __ldg(&verts[v*3+0]);
        const float b = __ldg(&verts[v*3+1]);
        const float c = __ldg(&verts[v*3+2]);
        x[u] = make_float2(a, a); y[u] = make_float2(b, b); z[u] = make_float2(c, c);
    }

    float2 acc[2][3][4];
    #pragma unroll
    for (int pr = 0; pr < 2; pr++)
        #pragma unroll
        for (int r = 0; r < 3; r++)
            #pragma unroll
            for (int u = 0; u < 4; u++)
                acc[pr][r][u] = make_float2(0.f, 0.f);

    const float* sWp = sW + vid * NJ;

    #pragma unroll 1
    for (int j = 0; j < NJ; j++) {
        float2 w[4];
        #pragma unroll
        for (int u = 0; u < 4; u++) {
            const float ww = sWp[u * (64*NJ) + j];
            w[u] = make_float2(ww, ww);
        }
        const float4* Aj = (const float4*)(sA2 + (j*NPAIR + 2*pg)*12);

        #pragma unroll
        for (int pr = 0; pr < 2; pr++) {
            const float4 q0 = Aj[pr*6+0], q1 = Aj[pr*6+1], q2 = Aj[pr*6+2];
            const float4 q3 = Aj[pr*6+3], q4 = Aj[pr*6+4], q5 = Aj[pr*6+5];
            const float2 m00 = make_float2(q0.x,q0.y), m01 = make_float2(q0.z,q0.w);
            const float2 m02 = make_float2(q1.x,q1.y), m03 = make_float2(q1.z,q1.w);
            const float2 m10 = make_float2(q2.x,q2.y), m11 = make_float2(q2.z,q2.w);
            const float2 m12 = make_float2(q3.x,q3.y), m13 = make_float2(q3.z,q3.w);
            const float2 m20 = make_float2(q4.x,q4.y), m21 = make_float2(q4.z,q4.w);
            const float2 m22 = make_float2(q5.x,q5.y), m23 = make_float2(q5.z,q5.w);

            #pragma unroll
            for (int u = 0; u < 4; u++) {
                float2 t;
                t = ffma2(m00, x[u], ffma2(m01, y[u], ffma2(m02, z[u], m03)));
                acc[pr][0][u] = ffma2(w[u], t, acc[pr][0][u]);
                t = ffma2(m10, x[u], ffma2(m11, y[u], ffma2(m12, z[u], m13)));
                acc[pr][1][u] = ffma2(w[u], t, acc[pr][1][u]);
                t = ffma2(m20, x[u], ffma2(m21, y[u], ffma2(m22, z[u], m23)));
                acc[pr][2][u] = ffma2(w[u], t, acc[pr][2][u]);
            }
        }
    }

    // Epilogue: add shift, scatter to out[p][v][a]
    #pragma unroll
    for (int pr = 0; pr < 2; pr++) {
        const int pairc = 2*pg + pr;
        const int p0 = 2*pairc;
        #pragma unroll
        for (int a = 0; a < 3; a++) {
            const float2 s = sSh[pairc*3 + a];
            #pragma unroll
            for (int u = 0; u < 4; u++) {
                const int v = v0 + 64*u;
                if (v < VTOT) {
                    out[ p0   *V3 + v*3 + a] = acc[pr][a][u].x + s.x;
                    out[(p0+1)*V3 + v*3 + a] = acc[pr][a][u].y + s.y;
                }
            }
        }
    }
}

// ---------------------------------------------------------------------------
extern "C" void kernel_launch(void* const* d_in, const int* in_sizes, int n_in,
                              void* d_out, int out_size)
{
    const float* vertices = (const float*)d_in[0];
    const float* joints   = (const float*)d_in[1];
    const float* weights  = (const float*)d_in[2];
    const float* disp     = (const float*)d_in[3];
    const float* rnd      = (const float*)d_in[4];
    Ptrs pp;
    for (int i = 0; i < 11; i++) pp.p[i] = (const float*)d_in[5 + i];
    float* out = (float*)d_out;

    const int nblocks = (VTOT + VPB - 1) / VPB;   // 1954
    lbs_all<<<nblocks, 256>>>(vertices, weights, joints, disp, rnd, pp, out);
}